// round 12
// baseline (speedup 1.0000x reference)
#include <cuda_runtime.h>
#include <cuda_bf16.h>
#include <cstdint>
#include <cmath>

#define I_DIM 512
#define H_DIM 512
#define KTOT  1024
#define NTOT  1024
#define BATCH 65536

// ---------------------------------------------------------------------------
// Device scratch
// W2: u4 index = ((nb*64 + kb)*2 + term)*32 + lane  (cols interleaved: 2j=tau, 2j+1=f;
//     k within each 16-block permuted: tile(2q,2q+1,2q+8,2q+9) <- global(4q..4q+3))
// ---------------------------------------------------------------------------
__device__ uint4  g_W2[(size_t)64 * 64 * 2 * 32];        // 4 MB
__device__ float  g_Y[(size_t)BATCH * H_DIM];            // 128 MB (pre-LN y)
__device__ float2 g_Spart[(size_t)BATCH * 8];            // 4 MB (LN partials, per bn)

__device__ __forceinline__ uint32_t smem_u32(const void* p) {
    uint32_t a;
    asm("{ .reg .u64 t; cvta.to.shared.u64 t, %1; cvt.u32.u64 %0, t; }"
        : "=r"(a) : "l"(p));
    return a;
}
__device__ __forceinline__ uint32_t pack_bf2(float a, float b) {
    __nv_bfloat16 ha = __float2bfloat16(a);
    __nv_bfloat16 hb = __float2bfloat16(b);
    return (uint32_t)__bfloat16_as_ushort(ha) |
           ((uint32_t)__bfloat16_as_ushort(hb) << 16);
}
__device__ __forceinline__ float bf_hi(float v) {
    return __bfloat162float(__float2bfloat16(v));
}
// d = {lo16: cvt(flo), hi16: cvt(fhi)}  (same packing as pack_bf2(flo, fhi))
#define PACK2(d, flo, fhi) \
    asm("cvt.rn.bf16x2.f32 %0, %1, %2;" : "=r"(d) : "f"(fhi), "f"(flo))
__device__ __forceinline__ float bflo_f(uint32_t r) { return __uint_as_float(r << 16); }
__device__ __forceinline__ float bfhi_f(uint32_t r) { return __uint_as_float(r & 0xffff0000u); }

__device__ __forceinline__ void mma16816(float* c, const uint4& a,
                                         uint32_t b0, uint32_t b1) {
    asm volatile(
        "mma.sync.aligned.m16n8k16.row.col.f32.bf16.bf16.f32 "
        "{%0,%1,%2,%3}, {%4,%5,%6,%7}, {%8,%9}, {%0,%1,%2,%3};"
        : "+f"(c[0]), "+f"(c[1]), "+f"(c[2]), "+f"(c[3])
        : "r"(a.x), "r"(a.y), "r"(a.z), "r"(a.w), "r"(b0), "r"(b1));
}
#define CP_ASYNC16(dst, src) \
    asm volatile("cp.async.cg.shared.global [%0], [%1], 16;" \
                 :: "r"(dst), "l"(src) : "memory")
#define CP_COMMIT() asm volatile("cp.async.commit_group;" ::: "memory")
#define CP_WAIT1()  asm volatile("cp.async.wait_group 1;" ::: "memory")
#define CP_WAIT0()  asm volatile("cp.async.wait_group 0;" ::: "memory")
#define LDS128(v, addr) \
    asm volatile("ld.shared.v4.u32 {%0,%1,%2,%3}, [%4];" \
        : "=r"((v).x), "=r"((v).y), "=r"((v).z), "=r"((v).w) : "r"(addr))

// ---------------------------------------------------------------------------
// Pack W (column interleave 2j=tau/2j+1=f AND k-permutation pi).
// ---------------------------------------------------------------------------
__device__ __forceinline__ float w_at2(const float* W_in, const float* W_rec,
                                       const float* W_tau, int c, int k) {
    int j = c >> 1;
    if ((c & 1) == 0) return W_tau[j * KTOT + k];
    return (k < I_DIM) ? W_in[j * I_DIM + k] : W_rec[j * H_DIM + (k - I_DIM)];
}

__global__ void pack_w_kernel(const float* __restrict__ W_in,
                              const float* __restrict__ W_rec,
                              const float* __restrict__ W_tau) {
    int t = blockIdx.x * blockDim.x + threadIdx.x;
    int lane = t & 31;
    int idx = t >> 5;
    int kb = idx & 63;
    int nb = idx >> 6;

    int n0 = nb * 16 + (lane >> 2);
    int k0 = kb * 16 + (lane & 3) * 4;   // pi: lane quad q owns global cols 4q..4q+3

    float v[8];
    v[0] = w_at2(W_in, W_rec, W_tau, n0,     k0);
    v[1] = w_at2(W_in, W_rec, W_tau, n0,     k0 + 1);
    v[2] = w_at2(W_in, W_rec, W_tau, n0,     k0 + 2);
    v[3] = w_at2(W_in, W_rec, W_tau, n0,     k0 + 3);
    v[4] = w_at2(W_in, W_rec, W_tau, n0 + 8, k0);
    v[5] = w_at2(W_in, W_rec, W_tau, n0 + 8, k0 + 1);
    v[6] = w_at2(W_in, W_rec, W_tau, n0 + 8, k0 + 2);
    v[7] = w_at2(W_in, W_rec, W_tau, n0 + 8, k0 + 3);

    uint4 hi, lo;
    hi.x = pack_bf2(v[0], v[1]); hi.y = pack_bf2(v[2], v[3]);
    hi.z = pack_bf2(v[4], v[5]); hi.w = pack_bf2(v[6], v[7]);
    lo.x = pack_bf2(v[0] - bf_hi(v[0]), v[1] - bf_hi(v[1]));
    lo.y = pack_bf2(v[2] - bf_hi(v[2]), v[3] - bf_hi(v[3]));
    lo.z = pack_bf2(v[4] - bf_hi(v[4]), v[5] - bf_hi(v[5]));
    lo.w = pack_bf2(v[6] - bf_hi(v[6]), v[7] - bf_hi(v[7]));

    size_t base = ((size_t)(nb * 64 + kb) * 2) * 32 + lane;
    g_W2[base]      = hi;
    g_W2[base + 32] = lo;
}

// ---------------------------------------------------------------------------
// GEMM + smem-staged fused epilogue.
// A: raw fp32 x/h streamed via cp.async (fragment-quad = contiguous 16B under pi),
//    converted to bf16 hi/lo in the consumer (no split_a kernel, no extra smem).
// B: 3-stage cp.async from pre-packed g_W2 (unchanged).
// Stage (32KB): A fp32 chunks [kb][mb][half][lane] @0 (16KB), B @16384 (16KB).
// ---------------------------------------------------------------------------
#define STAGE_BYTES 32768
#define N_STAGES 3
#define TPAD 68

__global__ __launch_bounds__(256)
void gemm_mma_kernel(const float* __restrict__ x,
                     const float* __restrict__ hin,
                     const float* __restrict__ b_in,
                     const float* __restrict__ b_tau,
                     float* __restrict__ out_tau) {
    extern __shared__ char smem[];
    const uint32_t sbase = smem_u32(smem);

    const int tid  = threadIdx.x;
    const int wid  = tid >> 5;
    const int lane = tid & 31;
    const int bn = blockIdx.x;            // 0..7
    const int bm = blockIdx.y;            // 0..511
    const int wm = wid & 1;
    const int wn = wid >> 1;

    // ---- A chunks (c = tid + j*256, j<4): lane=c&31, half=(c>>5)&1,
    //      mb=(c>>6)&7, kb=(c>>9)&1 ----
    uint32_t aoff[4];                      // float-index offset into x/h row space
    uint32_t asoff[4];
#pragma unroll
    for (int j = 0; j < 4; j++) {
        int c = tid + j * 256;
        int cl   = c & 31;
        int half = (c >> 5) & 1;
        int mb   = (c >> 6) & 7;
        int kb   = (c >> 9) & 1;
        int row  = bm * 128 + mb * 16 + (cl >> 2) + half * 8;
        aoff[j]  = (uint32_t)row * 512u + (uint32_t)(kb * 16 + (cl & 3) * 4);
        asoff[j] = (uint32_t)(c * 16);
    }
    // ---- B chunks (c = tid + j*256, j=4..7) ----
    uint32_t boff[4], bsoff[4];
#pragma unroll
    for (int j = 0; j < 4; j++) {
        int cb = tid + j * 256 + 1024 - 1024;  // cb = tid + j*256 within B region
        int cl   = cb & 31;
        int nb   = (cb >> 5) & 7;
        int term = (cb >> 8) & 1;
        int kb   = (cb >> 9) & 1;
        int nbg = bn * 8 + nb;
        boff[j]  = (uint32_t)(nbg * 4096 + kb * 64 + term * 32 + cl);
        bsoff[j] = (uint32_t)(16384 + cb * 16);
    }

    float acc[4][4][4];
#pragma unroll
    for (int a = 0; a < 4; a++)
#pragma unroll
        for (int b = 0; b < 4; b++)
#pragma unroll
            for (int d = 0; d < 4; d++) acc[a][b][d] = 0.f;

    // ---- prologue: stages 0,1 ----
#pragma unroll
    for (int s = 0; s < 2; s++) {
#pragma unroll
        for (int j = 0; j < 4; j++)
            CP_ASYNC16(sbase + s * STAGE_BYTES + asoff[j], x + aoff[j] + s * 32);
#pragma unroll
        for (int j = 0; j < 4; j++)
            CP_ASYNC16(sbase + s * STAGE_BYTES + bsoff[j],
                       g_W2 + (size_t)boff[j] + (size_t)s * 128);
        CP_COMMIT();
    }

    const int mbB = wm * 4;
    const int nbB = wn * 2;

    for (int i = 0; i < 32; i++) {
        CP_WAIT1();
        __syncthreads();

        if (i + 2 < 32) {
            uint32_t sb = sbase + ((i + 2) % N_STAGES) * STAGE_BYTES;
            const float* abase = (i + 2 < 16) ? x : hin;
            int col = ((i + 2) & 15) * 32;
#pragma unroll
            for (int j = 0; j < 4; j++)
                CP_ASYNC16(sb + asoff[j], abase + aoff[j] + col);
#pragma unroll
            for (int j = 0; j < 4; j++)
                CP_ASYNC16(sb + bsoff[j],
                           g_W2 + (size_t)boff[j] + (size_t)(i + 2) * 128);
        }
        CP_COMMIT();

        const uint32_t st = sbase + (i % N_STAGES) * STAGE_BYTES;
#pragma unroll
        for (int kb = 0; kb < 2; kb++) {
            uint4 ah[4], al[4], bh[2], bl[2];
#pragma unroll
            for (int mt = 0; mt < 4; mt++) {
                int mb = mbB + mt;
                uint32_t fb = st + (uint32_t)(((kb * 8 + mb) * 2) * 512) + lane * 16;
                uint4 w0, w1;
                LDS128(w0, fb);           // row r    : global cols 4q..4q+3
                LDS128(w1, fb + 512);     // row r+8
                // hi
                PACK2(ah[mt].x, __uint_as_float(w0.x), __uint_as_float(w0.y));
                PACK2(ah[mt].z, __uint_as_float(w0.z), __uint_as_float(w0.w));
                PACK2(ah[mt].y, __uint_as_float(w1.x), __uint_as_float(w1.y));
                PACK2(ah[mt].w, __uint_as_float(w1.z), __uint_as_float(w1.w));
                // lo residuals
                PACK2(al[mt].x, __uint_as_float(w0.x) - bflo_f(ah[mt].x),
                                __uint_as_float(w0.y) - bfhi_f(ah[mt].x));
                PACK2(al[mt].z, __uint_as_float(w0.z) - bflo_f(ah[mt].z),
                                __uint_as_float(w0.w) - bfhi_f(ah[mt].z));
                PACK2(al[mt].y, __uint_as_float(w1.x) - bflo_f(ah[mt].y),
                                __uint_as_float(w1.y) - bfhi_f(ah[mt].y));
                PACK2(al[mt].w, __uint_as_float(w1.z) - bflo_f(ah[mt].w),
                                __uint_as_float(w1.w) - bfhi_f(ah[mt].w));
            }
#pragma unroll
            for (int p = 0; p < 2; p++) {
                uint32_t bhi = st + 16384 + ((kb * 2 + 0) * 8 + nbB + p) * 512 + lane * 16;
                uint32_t blo = st + 16384 + ((kb * 2 + 1) * 8 + nbB + p) * 512 + lane * 16;
                LDS128(bh[p], bhi);
                LDS128(bl[p], blo);
            }
#pragma unroll
            for (int term = 0; term < 3; term++) {
#pragma unroll
                for (int mt = 0; mt < 4; mt++) {
#pragma unroll
                    for (int nt = 0; nt < 4; nt++) {
                        const uint4& A = (term == 2) ? al[mt] : ah[mt];
                        const uint4& B = (term == 1) ? bl[nt >> 1] : bh[nt >> 1];
                        uint32_t b0 = (nt & 1) ? B.z : B.x;
                        uint32_t b1 = (nt & 1) ? B.w : B.y;
                        mma16816(acc[mt][nt], A, b0, b1);
                    }
                }
            }
        }
    }

    // ---- tail: drain pipeline, then reuse smem for staging ----
    CP_WAIT0();
    __syncthreads();

    const uint32_t tauT = sbase;                  // [128][68] float
    const uint32_t fT   = sbase + 128 * TPAD * 4; // [128][68] float
    const int g  = lane >> 2;
    const int tg = lane & 3;

    // Phase 1: scatter raw pre-activations to smem
#pragma unroll
    for (int mt = 0; mt < 4; mt++) {
        int r0 = wm * 64 + mt * 16 + g;
        int r1 = r0 + 8;
#pragma unroll
        for (int nt = 0; nt < 4; nt++) {
            int jj = wn * 16 + nt * 4 + tg;
            asm volatile("st.shared.f32 [%0], %1;" :: "r"(tauT + (uint32_t)(r0 * TPAD + jj) * 4), "f"(acc[mt][nt][0]) : "memory");
            asm volatile("st.shared.f32 [%0], %1;" :: "r"(fT   + (uint32_t)(r0 * TPAD + jj) * 4), "f"(acc[mt][nt][1]) : "memory");
            asm volatile("st.shared.f32 [%0], %1;" :: "r"(tauT + (uint32_t)(r1 * TPAD + jj) * 4), "f"(acc[mt][nt][2]) : "memory");
            asm volatile("st.shared.f32 [%0], %1;" :: "r"(fT   + (uint32_t)(r1 * TPAD + jj) * 4), "f"(acc[mt][nt][3]) : "memory");
        }
    }
    __syncthreads();

    // Phase 2: coalesced writeout, h prefetched in batches of 4 (MLP=4).
    const int jj4 = tid & 15;
    const int rgrp = tid >> 4;
    const int jbase = bn * 64;
    const float4 bt4 = ((const float4*)b_tau)[jbase / 4 + jj4];
    const float4 bi4 = ((const float4*)b_in)[jbase / 4 + jj4];

#pragma unroll
    for (int half = 0; half < 2; half++) {
        float4 h4s[4];
#pragma unroll
        for (int u = 0; u < 4; u++) {
            int r = rgrp + (half * 4 + u) * 16;
            size_t row = (size_t)bm * 128 + r;
            h4s[u] = *((const float4*)(hin + row * H_DIM + jbase) + jj4);
        }
#pragma unroll
        for (int u = 0; u < 4; u++) {
            int r = rgrp + (half * 4 + u) * 16;
            size_t row = (size_t)bm * 128 + r;

            float4 tp, fp;
            LDS128(*(uint4*)&tp, tauT + (uint32_t)(r * TPAD + jj4 * 4) * 4);
            LDS128(*(uint4*)&fp, fT   + (uint32_t)(r * TPAD + jj4 * 4) * 4);
            float4 h4 = h4s[u];

            float4 tv, yv;
            float s = 0.f, q = 0.f;
            {
                const float* ptp = &tp.x; const float* pfp = &fp.x;
                const float* ph = &h4.x; const float* pbt = &bt4.x; const float* pbi = &bi4.x;
                float* ptv = &tv.x; float* pyv = &yv.x;
#pragma unroll
                for (int c = 0; c < 4; c++) {
                    float tau = 0.5f + 4.5f / (1.0f + __expf(-(ptp[c] + pbt[c])));
                    float f   = tanhf(pfp[c] + pbi[c]);
                    float yy  = ph[c] + 0.1f * (f - ph[c]) / tau;
                    ptv[c] = tau; pyv[c] = yy;
                    s += yy; q += yy * yy;
                }
            }
            *((float4*)(out_tau + row * H_DIM + jbase) + jj4) = tv;
            *((float4*)(g_Y + row * H_DIM + jbase) + jj4) = yv;

            s += __shfl_xor_sync(0xffffffffu, s, 1);
            q += __shfl_xor_sync(0xffffffffu, q, 1);
            s += __shfl_xor_sync(0xffffffffu, s, 2);
            q += __shfl_xor_sync(0xffffffffu, q, 2);
            s += __shfl_xor_sync(0xffffffffu, s, 4);
            q += __shfl_xor_sync(0xffffffffu, q, 4);
            s += __shfl_xor_sync(0xffffffffu, s, 8);
            q += __shfl_xor_sync(0xffffffffu, q, 8);
            if (jj4 == 0)
                g_Spart[row * 8 + bn] = make_float2(s, q);
        }
    }
}

// ---------------------------------------------------------------------------
// Finalize: 4 rows / 256-thread block, 2 float4 per thread, y-loads early.
// ---------------------------------------------------------------------------
__global__ __launch_bounds__(256)
void finalize_kernel(const float* __restrict__ gamma, const float* __restrict__ beta,
                     float* __restrict__ out_h) {
    const int tid = threadIdx.x;
    const size_t row0 = (size_t)blockIdx.x * 4;
    const int r = tid >> 6;
    const int t = tid & 63;
    const size_t row = row0 + r;

    float4 ya = *((const float4*)(g_Y + row * H_DIM) + t);
    float4 yb = *((const float4*)(g_Y + row * H_DIM) + t + 64);

    __shared__ float2 mv[4];
    if (tid < 32) {
        int rr = tid >> 3, part = tid & 7;
        float2 p = g_Spart[(row0 + rr) * 8 + part];
        float s = p.x, q = p.y;
        s += __shfl_xor_sync(0xffffffffu, s, 1);
        q += __shfl_xor_sync(0xffffffffu, q, 1);
        s += __shfl_xor_sync(0xffffffffu, s, 2);
        q += __shfl_xor_sync(0xffffffffu, q, 2);
        s += __shfl_xor_sync(0xffffffffu, s, 4);
        q += __shfl_xor_sync(0xffffffffu, q, 4);
        if (part == 0) {
            float mu  = s * (1.0f / H_DIM);
            float var = q * (1.0f / H_DIM) - mu * mu;
            mv[rr] = make_float2(mu, rsqrtf(var + 1e-5f));
        }
    }
    __syncthreads();

    float mu  = mv[r].x;
    float inv = mv[r].y;

    float4 ga = ((const float4*)gamma)[t];
    float4 gb = ((const float4*)gamma)[t + 64];
    float4 ba = ((const float4*)beta)[t];
    float4 bb = ((const float4*)beta)[t + 64];

    float4 oa, ob;
    oa.x = (ya.x - mu) * inv * ga.x + ba.x;
    oa.y = (ya.y - mu) * inv * ga.y + ba.y;
    oa.z = (ya.z - mu) * inv * ga.z + ba.z;
    oa.w = (ya.w - mu) * inv * ga.w + ba.w;
    ob.x = (yb.x - mu) * inv * gb.x + bb.x;
    ob.y = (yb.y - mu) * inv * gb.y + bb.y;
    ob.z = (yb.z - mu) * inv * gb.z + bb.z;
    ob.w = (yb.w - mu) * inv * gb.w + bb.w;

    *((float4*)(out_h + row * H_DIM) + t) = oa;
    *((float4*)(out_h + row * H_DIM) + t + 64) = ob;
}

// ---------------------------------------------------------------------------
extern "C" void kernel_launch(void* const* d_in, const int* in_sizes, int n_in,
                              void* d_out, int out_size) {
    const float* x     = (const float*)d_in[0];
    const float* h     = (const float*)d_in[1];
    const float* W_in  = (const float*)d_in[2];
    const float* b_in  = (const float*)d_in[3];
    const float* W_rec = (const float*)d_in[4];
    const float* W_tau = (const float*)d_in[5];
    const float* b_tau = (const float*)d_in[6];
    const float* gamma = (const float*)d_in[7];
    const float* beta  = (const float*)d_in[8];

    const int B = in_sizes[0] / I_DIM;    // 65536

    float* out = (float*)d_out;
    float* out_h   = out;
    float* out_tau = out + (size_t)B * H_DIM;

    pack_w_kernel<<<512, 256>>>(W_in, W_rec, W_tau);

    cudaFuncSetAttribute(gemm_mma_kernel,
                         cudaFuncAttributeMaxDynamicSharedMemorySize,
                         N_STAGES * STAGE_BYTES);
    dim3 ggrid(NTOT / 128, B / 128);      // (8, 512)
    gemm_mma_kernel<<<ggrid, 256, N_STAGES * STAGE_BYTES>>>(x, h, b_in, b_tau, out_tau);

    finalize_kernel<<<B / 4, 256>>>(gamma, beta, out_h);
}

// round 13
// speedup vs baseline: 1.0524x; 1.0524x over previous
#include <cuda_runtime.h>
#include <cuda_bf16.h>
#include <cstdint>
#include <cmath>

#define I_DIM 512
#define H_DIM 512
#define KTOT  1024
#define NTOT  1024
#define BATCH 65536

// ---------------------------------------------------------------------------
// Device scratch
// A2: u4 index = ((rb*64 + kb)*2 + term)*32 + lane
// W2: u4 index = ((nb*64 + kb)*2 + term)*32 + lane  (cols interleaved: 2j=tau, 2j+1=f)
// ---------------------------------------------------------------------------
__device__ uint4  g_A2[(size_t)4096 * 64 * 2 * 32];      // 256 MB
__device__ uint4  g_W2[(size_t)64 * 64 * 2 * 32];        // 4 MB
__device__ float  g_Y[(size_t)BATCH * H_DIM];            // 128 MB (pre-LN y)
__device__ float2 g_Spart[(size_t)BATCH * 8];            // 4 MB (LN partials, per bn)

__device__ __forceinline__ uint32_t smem_u32(const void* p) {
    uint32_t a;
    asm("{ .reg .u64 t; cvta.to.shared.u64 t, %1; cvt.u32.u64 %0, t; }"
        : "=r"(a) : "l"(p));
    return a;
}
__device__ __forceinline__ uint32_t pack_bf2(float a, float b) {
    __nv_bfloat16 ha = __float2bfloat16(a);
    __nv_bfloat16 hb = __float2bfloat16(b);
    return (uint32_t)__bfloat16_as_ushort(ha) |
           ((uint32_t)__bfloat16_as_ushort(hb) << 16);
}
__device__ __forceinline__ float bf_hi(float v) {
    return __bfloat162float(__float2bfloat16(v));
}
__device__ __forceinline__ void mma16816(float* c, const uint4& a,
                                         uint32_t b0, uint32_t b1) {
    asm volatile(
        "mma.sync.aligned.m16n8k16.row.col.f32.bf16.bf16.f32 "
        "{%0,%1,%2,%3}, {%4,%5,%6,%7}, {%8,%9}, {%0,%1,%2,%3};"
        : "+f"(c[0]), "+f"(c[1]), "+f"(c[2]), "+f"(c[3])
        : "r"(a.x), "r"(a.y), "r"(a.z), "r"(a.w), "r"(b0), "r"(b1));
}
#define CP_ASYNC16(dst, src) \
    asm volatile("cp.async.cg.shared.global [%0], [%1], 16;" \
                 :: "r"(dst), "l"(src) : "memory")
#define CP_COMMIT() asm volatile("cp.async.commit_group;" ::: "memory")
#define CP_WAIT1()  asm volatile("cp.async.wait_group 1;" ::: "memory")
#define CP_WAIT0()  asm volatile("cp.async.wait_group 0;" ::: "memory")
#define LDS128(v, addr) \
    asm volatile("ld.shared.v4.u32 {%0,%1,%2,%3}, [%4];" \
        : "=r"((v).x), "=r"((v).y), "=r"((v).z), "=r"((v).w) : "r"(addr))

// ---------------------------------------------------------------------------
// W element fetch (interleaved columns: packed col c -> j=c>>1; even=tau, odd=f).
// ---------------------------------------------------------------------------
__device__ __forceinline__ float w_at2(const float* W_in, const float* W_rec,
                                       const float* W_tau, int c, int k) {
    int j = c >> 1;
    if ((c & 1) == 0) return W_tau[j * KTOT + k];
    return (k < I_DIM) ? W_in[j * I_DIM + k] : W_rec[j * H_DIM + (k - I_DIM)];
}

// ---------------------------------------------------------------------------
// Combined prep kernel:
//   blocks 0..4095   : split A = [x|h] into fragment-linear hi/lo bf16 tiles
//   blocks 4096..4607: pack W into fragment-linear hi/lo bf16 tiles
// ---------------------------------------------------------------------------
__global__ __launch_bounds__(256)
void prep_kernel(const float* __restrict__ x, const float* __restrict__ h,
                 const float* __restrict__ W_in, const float* __restrict__ W_rec,
                 const float* __restrict__ W_tau) {
    const int tid = threadIdx.x;
    const int lane = tid & 31;

    if (blockIdx.x < 4096) {
        // ---- split A ----
        const int rb = blockIdx.x;
        const int wid = tid >> 5;

        const int r0 = lane >> 2;
        const int cq = (lane & 3) * 2;
        const size_t rowA = (size_t)rb * 16 + r0;
        const size_t rowB = rowA + 8;

#pragma unroll
        for (int j = 0; j < 8; j++) {
            int kb = wid * 8 + j;
            int kg = kb * 16 + cq;
            const float* srcA;
            const float* srcB;
            if (kb < 32) { srcA = x + rowA * I_DIM + kg;          srcB = x + rowB * I_DIM + kg; }
            else         { srcA = h + rowA * H_DIM + (kg - 512);  srcB = h + rowB * H_DIM + (kg - 512); }

            float a0 = srcA[0], a1 = srcA[1], a2 = srcA[8], a3 = srcA[9];
            float b0 = srcB[0], b1 = srcB[1], b2 = srcB[8], b3 = srcB[9];

            uint4 hi, lo;
            hi.x = pack_bf2(a0, a1); hi.y = pack_bf2(b0, b1);
            hi.z = pack_bf2(a2, a3); hi.w = pack_bf2(b2, b3);
            lo.x = pack_bf2(a0 - bf_hi(a0), a1 - bf_hi(a1));
            lo.y = pack_bf2(b0 - bf_hi(b0), b1 - bf_hi(b1));
            lo.z = pack_bf2(a2 - bf_hi(a2), a3 - bf_hi(a3));
            lo.w = pack_bf2(b2 - bf_hi(b2), b3 - bf_hi(b3));

            size_t base = ((size_t)(rb * 64 + kb) * 2) * 32 + lane;
            g_A2[base]      = hi;
            g_A2[base + 32] = lo;
        }
    } else {
        // ---- pack W ----
        int t = (blockIdx.x - 4096) * blockDim.x + tid;
        int idx = t >> 5;
        int kb = idx & 63;
        int nb = idx >> 6;

        int n0 = nb * 16 + (lane >> 2);
        int k0 = kb * 16 + (lane & 3) * 2;

        float v[8];
        v[0] = w_at2(W_in, W_rec, W_tau, n0,     k0);
        v[1] = w_at2(W_in, W_rec, W_tau, n0,     k0 + 1);
        v[2] = w_at2(W_in, W_rec, W_tau, n0,     k0 + 8);
        v[3] = w_at2(W_in, W_rec, W_tau, n0,     k0 + 9);
        v[4] = w_at2(W_in, W_rec, W_tau, n0 + 8, k0);
        v[5] = w_at2(W_in, W_rec, W_tau, n0 + 8, k0 + 1);
        v[6] = w_at2(W_in, W_rec, W_tau, n0 + 8, k0 + 8);
        v[7] = w_at2(W_in, W_rec, W_tau, n0 + 8, k0 + 9);

        uint4 hi, lo;
        hi.x = pack_bf2(v[0], v[1]); hi.y = pack_bf2(v[2], v[3]);
        hi.z = pack_bf2(v[4], v[5]); hi.w = pack_bf2(v[6], v[7]);
        lo.x = pack_bf2(v[0] - bf_hi(v[0]), v[1] - bf_hi(v[1]));
        lo.y = pack_bf2(v[2] - bf_hi(v[2]), v[3] - bf_hi(v[3]));
        lo.z = pack_bf2(v[4] - bf_hi(v[4]), v[5] - bf_hi(v[5]));
        lo.w = pack_bf2(v[6] - bf_hi(v[6]), v[7] - bf_hi(v[7]));

        size_t base = ((size_t)(nb * 64 + kb) * 2) * 32 + lane;
        g_W2[base]      = hi;
        g_W2[base + 32] = lo;
    }
}

// ---------------------------------------------------------------------------
// GEMM + smem-staged fused epilogue (R11, verbatim).
// CTA 128x128, warp 64x32 (2x4), BK=32, 3-stage cp.async, single barrier/iter.
// ---------------------------------------------------------------------------
#define STAGE_BYTES 32768
#define N_STAGES 3
#define TPAD 68

__global__ __launch_bounds__(256)
void gemm_mma_kernel(const float* __restrict__ hin,
                     const float* __restrict__ b_in,
                     const float* __restrict__ b_tau,
                     float* __restrict__ out_tau) {
    extern __shared__ char smem[];
    const uint32_t sbase = smem_u32(smem);

    const int tid  = threadIdx.x;
    const int wid  = tid >> 5;
    const int lane = tid & 31;
    const int bn = blockIdx.x;            // 0..7
    const int bm = blockIdx.y;            // 0..511
    const int wm = wid & 1;
    const int wn = wid >> 1;

    uint32_t soff[8];
    const uint4* gptr[8];
#pragma unroll
    for (int j = 0; j < 8; j++) {
        int c = tid + j * 256;
        int cl   = c & 31;
        int blk  = (c >> 5) & 7;
        int term = (c >> 8) & 1;
        int kb   = (c >> 9) & 1;
        if (c < 1024) {
            int rb = bm * 8 + blk;
            gptr[j] = g_A2 + (((size_t)(rb * 64 + kb) * 2 + term) * 32 + cl);
        } else {
            int nb = bn * 8 + blk;
            gptr[j] = g_W2 + (((size_t)(nb * 64 + kb) * 2 + term) * 32 + cl);
        }
        soff[j] = (uint32_t)(c * 16);
    }

    float acc[4][4][4];
#pragma unroll
    for (int a = 0; a < 4; a++)
#pragma unroll
        for (int b = 0; b < 4; b++)
#pragma unroll
            for (int d = 0; d < 4; d++) acc[a][b][d] = 0.f;

#pragma unroll
    for (int s = 0; s < 2; s++) {
#pragma unroll
        for (int j = 0; j < 8; j++)
            CP_ASYNC16(sbase + s * STAGE_BYTES + soff[j], gptr[j] + (size_t)s * 128);
        CP_COMMIT();
    }

    const int mbB = wm * 4;
    const int nbB = wn * 2;

    for (int i = 0; i < 32; i++) {
        CP_WAIT1();
        __syncthreads();

        if (i + 2 < 32) {
            uint32_t sb = sbase + ((i + 2) % N_STAGES) * STAGE_BYTES;
#pragma unroll
            for (int j = 0; j < 8; j++)
                CP_ASYNC16(sb + soff[j], gptr[j] + (size_t)(i + 2) * 128);
        }
        CP_COMMIT();

        const uint32_t st = sbase + (i % N_STAGES) * STAGE_BYTES;
#pragma unroll
        for (int kb = 0; kb < 2; kb++) {
            uint4 ah[4], al[4], bh[2], bl[2];
#pragma unroll
            for (int mb = 0; mb < 4; mb++) {
                uint32_t ahi = st + ((kb * 2 + 0) * 8 + mbB + mb) * 512 + lane * 16;
                uint32_t alo = st + ((kb * 2 + 1) * 8 + mbB + mb) * 512 + lane * 16;
                LDS128(ah[mb], ahi);
                LDS128(al[mb], alo);
            }
#pragma unroll
            for (int p = 0; p < 2; p++) {
                uint32_t bhi = st + 16384 + ((kb * 2 + 0) * 8 + nbB + p) * 512 + lane * 16;
                uint32_t blo = st + 16384 + ((kb * 2 + 1) * 8 + nbB + p) * 512 + lane * 16;
                LDS128(bh[p], bhi);
                LDS128(bl[p], blo);
            }
#pragma unroll
            for (int term = 0; term < 3; term++) {
#pragma unroll
                for (int mt = 0; mt < 4; mt++) {
#pragma unroll
                    for (int nt = 0; nt < 4; nt++) {
                        const uint4& A = (term == 2) ? al[mt] : ah[mt];
                        const uint4& B = (term == 1) ? bl[nt >> 1] : bh[nt >> 1];
                        uint32_t b0 = (nt & 1) ? B.z : B.x;
                        uint32_t b1 = (nt & 1) ? B.w : B.y;
                        mma16816(acc[mt][nt], A, b0, b1);
                    }
                }
            }
        }
    }

    // ---- tail: drain pipeline, then reuse smem for staging ----
    CP_WAIT0();
    __syncthreads();

    const uint32_t tauT = sbase;                  // [128][68] float
    const uint32_t fT   = sbase + 128 * TPAD * 4; // [128][68] float
    const int g  = lane >> 2;
    const int tg = lane & 3;

    // Phase 1: scatter raw pre-activations to smem
#pragma unroll
    for (int mt = 0; mt < 4; mt++) {
        int r0 = wm * 64 + mt * 16 + g;
        int r1 = r0 + 8;
#pragma unroll
        for (int nt = 0; nt < 4; nt++) {
            int jj = wn * 16 + nt * 4 + tg;
            asm volatile("st.shared.f32 [%0], %1;" :: "r"(tauT + (uint32_t)(r0 * TPAD + jj) * 4), "f"(acc[mt][nt][0]) : "memory");
            asm volatile("st.shared.f32 [%0], %1;" :: "r"(fT   + (uint32_t)(r0 * TPAD + jj) * 4), "f"(acc[mt][nt][1]) : "memory");
            asm volatile("st.shared.f32 [%0], %1;" :: "r"(tauT + (uint32_t)(r1 * TPAD + jj) * 4), "f"(acc[mt][nt][2]) : "memory");
            asm volatile("st.shared.f32 [%0], %1;" :: "r"(fT   + (uint32_t)(r1 * TPAD + jj) * 4), "f"(acc[mt][nt][3]) : "memory");
        }
    }
    __syncthreads();

    // Phase 2: coalesced writeout, h prefetched in batches of 4 (MLP=4).
    const int jj4 = tid & 15;
    const int rgrp = tid >> 4;
    const int jbase = bn * 64;
    const float4 bt4 = ((const float4*)b_tau)[jbase / 4 + jj4];
    const float4 bi4 = ((const float4*)b_in)[jbase / 4 + jj4];

#pragma unroll
    for (int half = 0; half < 2; half++) {
        float4 h4s[4];
#pragma unroll
        for (int u = 0; u < 4; u++) {
            int r = rgrp + (half * 4 + u) * 16;
            size_t row = (size_t)bm * 128 + r;
            h4s[u] = *((const float4*)(hin + row * H_DIM + jbase) + jj4);
        }
#pragma unroll
        for (int u = 0; u < 4; u++) {
            int r = rgrp + (half * 4 + u) * 16;
            size_t row = (size_t)bm * 128 + r;

            float4 tp, fp;
            LDS128(*(uint4*)&tp, tauT + (uint32_t)(r * TPAD + jj4 * 4) * 4);
            LDS128(*(uint4*)&fp, fT   + (uint32_t)(r * TPAD + jj4 * 4) * 4);
            float4 h4 = h4s[u];

            float4 tv, yv;
            float s = 0.f, q = 0.f;
            {
                const float* ptp = &tp.x; const float* pfp = &fp.x;
                const float* ph = &h4.x; const float* pbt = &bt4.x; const float* pbi = &bi4.x;
                float* ptv = &tv.x; float* pyv = &yv.x;
#pragma unroll
                for (int c = 0; c < 4; c++) {
                    float tau = 0.5f + 4.5f / (1.0f + __expf(-(ptp[c] + pbt[c])));
                    float f   = tanhf(pfp[c] + pbi[c]);
                    float yy  = ph[c] + 0.1f * (f - ph[c]) / tau;
                    ptv[c] = tau; pyv[c] = yy;
                    s += yy; q += yy * yy;
                }
            }
            *((float4*)(out_tau + row * H_DIM + jbase) + jj4) = tv;
            *((float4*)(g_Y + row * H_DIM + jbase) + jj4) = yv;

            s += __shfl_xor_sync(0xffffffffu, s, 1);
            q += __shfl_xor_sync(0xffffffffu, q, 1);
            s += __shfl_xor_sync(0xffffffffu, s, 2);
            q += __shfl_xor_sync(0xffffffffu, q, 2);
            s += __shfl_xor_sync(0xffffffffu, s, 4);
            q += __shfl_xor_sync(0xffffffffu, q, 4);
            s += __shfl_xor_sync(0xffffffffu, s, 8);
            q += __shfl_xor_sync(0xffffffffu, q, 8);
            if (jj4 == 0)
                g_Spart[row * 8 + bn] = make_float2(s, q);
        }
    }
}

// ---------------------------------------------------------------------------
// Finalize (R11 verbatim): 4 rows/block, 2 float4/thread, y-loads early.
// ---------------------------------------------------------------------------
__global__ __launch_bounds__(256)
void finalize_kernel(const float* __restrict__ gamma, const float* __restrict__ beta,
                     float* __restrict__ out_h) {
    const int tid = threadIdx.x;
    const size_t row0 = (size_t)blockIdx.x * 4;
    const int r = tid >> 6;
    const int t = tid & 63;
    const size_t row = row0 + r;

    float4 ya = *((const float4*)(g_Y + row * H_DIM) + t);
    float4 yb = *((const float4*)(g_Y + row * H_DIM) + t + 64);

    __shared__ float2 mv[4];
    if (tid < 32) {
        int rr = tid >> 3, part = tid & 7;
        float2 p = g_Spart[(row0 + rr) * 8 + part];
        float s = p.x, q = p.y;
        s += __shfl_xor_sync(0xffffffffu, s, 1);
        q += __shfl_xor_sync(0xffffffffu, q, 1);
        s += __shfl_xor_sync(0xffffffffu, s, 2);
        q += __shfl_xor_sync(0xffffffffu, q, 2);
        s += __shfl_xor_sync(0xffffffffu, s, 4);
        q += __shfl_xor_sync(0xffffffffu, q, 4);
        if (part == 0) {
            float mu  = s * (1.0f / H_DIM);
            float var = q * (1.0f / H_DIM) - mu * mu;
            mv[rr] = make_float2(mu, rsqrtf(var + 1e-5f));
        }
    }
    __syncthreads();

    float mu  = mv[r].x;
    float inv = mv[r].y;

    float4 ga = ((const float4*)gamma)[t];
    float4 gb = ((const float4*)gamma)[t + 64];
    float4 ba = ((const float4*)beta)[t];
    float4 bb = ((const float4*)beta)[t + 64];

    float4 oa, ob;
    oa.x = (ya.x - mu) * inv * ga.x + ba.x;
    oa.y = (ya.y - mu) * inv * ga.y + ba.y;
    oa.z = (ya.z - mu) * inv * ga.z + ba.z;
    oa.w = (ya.w - mu) * inv * ga.w + ba.w;
    ob.x = (yb.x - mu) * inv * gb.x + bb.x;
    ob.y = (yb.y - mu) * inv * gb.y + bb.y;
    ob.z = (yb.z - mu) * inv * gb.z + bb.z;
    ob.w = (yb.w - mu) * inv * gb.w + bb.w;

    *((float4*)(out_h + row * H_DIM) + t) = oa;
    *((float4*)(out_h + row * H_DIM) + t + 64) = ob;
}

// ---------------------------------------------------------------------------
extern "C" void kernel_launch(void* const* d_in, const int* in_sizes, int n_in,
                              void* d_out, int out_size) {
    const float* x     = (const float*)d_in[0];
    const float* h     = (const float*)d_in[1];
    const float* W_in  = (const float*)d_in[2];
    const float* b_in  = (const float*)d_in[3];
    const float* W_rec = (const float*)d_in[4];
    const float* W_tau = (const float*)d_in[5];
    const float* b_tau = (const float*)d_in[6];
    const float* gamma = (const float*)d_in[7];
    const float* beta  = (const float*)d_in[8];

    const int B = in_sizes[0] / I_DIM;    // 65536

    float* out = (float*)d_out;
    float* out_h   = out;
    float* out_tau = out + (size_t)B * H_DIM;

    // combined A-split + W-pack (4096 + 512 blocks)
    prep_kernel<<<B / 16 + 512, 256>>>(x, h, W_in, W_rec, W_tau);

    cudaFuncSetAttribute(gemm_mma_kernel,
                         cudaFuncAttributeMaxDynamicSharedMemorySize,
                         N_STAGES * STAGE_BYTES);
    dim3 ggrid(NTOT / 128, B / 128);      // (8, 512)
    gemm_mma_kernel<<<ggrid, 256, N_STAGES * STAGE_BYTES>>>(h, b_in, b_tau, out_tau);

    finalize_kernel<<<B / 4, 256>>>(gamma, beta, out_h);
}

// round 14
// speedup vs baseline: 1.0561x; 1.0035x over previous
#include <cuda_runtime.h>
#include <cuda_bf16.h>
#include <cstdint>
#include <cmath>

#define I_DIM 512
#define H_DIM 512
#define KTOT  1024
#define NTOT  1024
#define BATCH 65536

// ---------------------------------------------------------------------------
// Device scratch
// A2: u4 index = ((rb*64 + kb)*2 + term)*32 + lane
// W2: u4 index = ((nb*64 + kb)*2 + term)*32 + lane
// Both use column interleave (2j=tau, 2j+1=f) on W and k-permutation pi:
//   tile positions (2q,2q+1,2q+8,2q+9)  <-  global k = kb*16 + (4q..4q+3)
// ---------------------------------------------------------------------------
__device__ uint4  g_A2[(size_t)4096 * 64 * 2 * 32];      // 256 MB
__device__ uint4  g_W2[(size_t)64 * 64 * 2 * 32];        // 4 MB
__device__ float  g_Y[(size_t)BATCH * H_DIM];            // 128 MB (pre-LN y)
__device__ float2 g_Spart[(size_t)BATCH * 8];            // 4 MB (LN partials, per bn)

__device__ __forceinline__ uint32_t smem_u32(const void* p) {
    uint32_t a;
    asm("{ .reg .u64 t; cvta.to.shared.u64 t, %1; cvt.u32.u64 %0, t; }"
        : "=r"(a) : "l"(p));
    return a;
}
__device__ __forceinline__ uint32_t pack_bf2(float a, float b) {
    __nv_bfloat16 ha = __float2bfloat16(a);
    __nv_bfloat16 hb = __float2bfloat16(b);
    return (uint32_t)__bfloat16_as_ushort(ha) |
           ((uint32_t)__bfloat16_as_ushort(hb) << 16);
}
__device__ __forceinline__ float bf_hi(float v) {
    return __bfloat162float(__float2bfloat16(v));
}
__device__ __forceinline__ void mma16816(float* c, const uint4& a,
                                         uint32_t b0, uint32_t b1) {
    asm volatile(
        "mma.sync.aligned.m16n8k16.row.col.f32.bf16.bf16.f32 "
        "{%0,%1,%2,%3}, {%4,%5,%6,%7}, {%8,%9}, {%0,%1,%2,%3};"
        : "+f"(c[0]), "+f"(c[1]), "+f"(c[2]), "+f"(c[3])
        : "r"(a.x), "r"(a.y), "r"(a.z), "r"(a.w), "r"(b0), "r"(b1));
}
#define CP_ASYNC16(dst, src) \
    asm volatile("cp.async.cg.shared.global [%0], [%1], 16;" \
                 :: "r"(dst), "l"(src) : "memory")
#define CP_COMMIT() asm volatile("cp.async.commit_group;" ::: "memory")
#define CP_WAIT1()  asm volatile("cp.async.wait_group 1;" ::: "memory")
#define CP_WAIT0()  asm volatile("cp.async.wait_group 0;" ::: "memory")
#define LDS128(v, addr) \
    asm volatile("ld.shared.v4.u32 {%0,%1,%2,%3}, [%4];" \
        : "=r"((v).x), "=r"((v).y), "=r"((v).z), "=r"((v).w) : "r"(addr))

// ---------------------------------------------------------------------------
// W element fetch (interleaved columns: packed col c -> j=c>>1; even=tau, odd=f).
// ---------------------------------------------------------------------------
__device__ __forceinline__ float w_at2(const float* W_in, const float* W_rec,
                                       const float* W_tau, int c, int k) {
    int j = c >> 1;
    if ((c & 1) == 0) return W_tau[j * KTOT + k];
    return (k < I_DIM) ? W_in[j * I_DIM + k] : W_rec[j * H_DIM + (k - I_DIM)];
}

// ---------------------------------------------------------------------------
// Combined prep kernel (k-permutation pi applied to BOTH A and W):
//   blocks 0..4095   : split A = [x|h]; lane loads ONE float4 per row per kb
//   blocks 4096..4607: pack W (same pi; fragment order per R12)
// ---------------------------------------------------------------------------
__global__ __launch_bounds__(256)
void prep_kernel(const float* __restrict__ x, const float* __restrict__ h,
                 const float* __restrict__ W_in, const float* __restrict__ W_rec,
                 const float* __restrict__ W_tau) {
    const int tid = threadIdx.x;
    const int lane = tid & 31;

    if (blockIdx.x < 4096) {
        // ---- split A (pi: lane quad q owns global cols 4q..4q+3) ----
        const int rb = blockIdx.x;
        const int wid = tid >> 5;

        const int r0 = lane >> 2;
        const int tg4 = (lane & 3) * 4;
        const size_t rowA = (size_t)rb * 16 + r0;
        const size_t rowB = rowA + 8;

#pragma unroll
        for (int j = 0; j < 8; j++) {
            int kb = wid * 8 + j;
            int kg = kb * 16 + tg4;
            const float* srcA;
            const float* srcB;
            if (kb < 32) { srcA = x + rowA * I_DIM + kg;          srcB = x + rowB * I_DIM + kg; }
            else         { srcA = h + rowA * H_DIM + (kg - 512);  srcB = h + rowB * H_DIM + (kg - 512); }

            float4 va = *(const float4*)srcA;
            float4 vb = *(const float4*)srcB;

            uint4 hi, lo;
            // tile positions: x=(rowA, 2q..2q+1), y=(rowB, same), z=(rowA, 2q+8..9), w=(rowB, same)
            hi.x = pack_bf2(va.x, va.y); hi.y = pack_bf2(vb.x, vb.y);
            hi.z = pack_bf2(va.z, va.w); hi.w = pack_bf2(vb.z, vb.w);
            lo.x = pack_bf2(va.x - bf_hi(va.x), va.y - bf_hi(va.y));
            lo.y = pack_bf2(vb.x - bf_hi(vb.x), vb.y - bf_hi(vb.y));
            lo.z = pack_bf2(va.z - bf_hi(va.z), va.w - bf_hi(va.w));
            lo.w = pack_bf2(vb.z - bf_hi(vb.z), vb.w - bf_hi(vb.w));

            size_t base = ((size_t)(rb * 64 + kb) * 2) * 32 + lane;
            g_A2[base]      = hi;
            g_A2[base + 32] = lo;
        }
    } else {
        // ---- pack W (pi; fragment order: x=(n0,lo-pair), y=(n0,hi-pair),
        //      z=(n0+8,lo-pair), w=(n0+8,hi-pair)) ----
        int t = (blockIdx.x - 4096) * blockDim.x + tid;
        int idx = t >> 5;
        int kb = idx & 63;
        int nb = idx >> 6;

        int n0 = nb * 16 + (lane >> 2);
        int k0 = kb * 16 + (lane & 3) * 4;

        float v[8];
        v[0] = w_at2(W_in, W_rec, W_tau, n0,     k0);
        v[1] = w_at2(W_in, W_rec, W_tau, n0,     k0 + 1);
        v[2] = w_at2(W_in, W_rec, W_tau, n0,     k0 + 2);
        v[3] = w_at2(W_in, W_rec, W_tau, n0,     k0 + 3);
        v[4] = w_at2(W_in, W_rec, W_tau, n0 + 8, k0);
        v[5] = w_at2(W_in, W_rec, W_tau, n0 + 8, k0 + 1);
        v[6] = w_at2(W_in, W_rec, W_tau, n0 + 8, k0 + 2);
        v[7] = w_at2(W_in, W_rec, W_tau, n0 + 8, k0 + 3);

        uint4 hi, lo;
        hi.x = pack_bf2(v[0], v[1]); hi.y = pack_bf2(v[2], v[3]);
        hi.z = pack_bf2(v[4], v[5]); hi.w = pack_bf2(v[6], v[7]);
        lo.x = pack_bf2(v[0] - bf_hi(v[0]), v[1] - bf_hi(v[1]));
        lo.y = pack_bf2(v[2] - bf_hi(v[2]), v[3] - bf_hi(v[3]));
        lo.z = pack_bf2(v[4] - bf_hi(v[4]), v[5] - bf_hi(v[5]));
        lo.w = pack_bf2(v[6] - bf_hi(v[6]), v[7] - bf_hi(v[7]));

        size_t base = ((size_t)(nb * 64 + kb) * 2) * 32 + lane;
        g_W2[base]      = hi;
        g_W2[base + 32] = lo;
    }
}

// ---------------------------------------------------------------------------
// GEMM + smem-staged fused epilogue (R13 verbatim — layout-agnostic to pi).
// ---------------------------------------------------------------------------
#define STAGE_BYTES 32768
#define N_STAGES 3
#define TPAD 68

__global__ __launch_bounds__(256)
void gemm_mma_kernel(const float* __restrict__ hin,
                     const float* __restrict__ b_in,
                     const float* __restrict__ b_tau,
                     float* __restrict__ out_tau) {
    extern __shared__ char smem[];
    const uint32_t sbase = smem_u32(smem);

    const int tid  = threadIdx.x;
    const int wid  = tid >> 5;
    const int lane = tid & 31;
    const int bn = blockIdx.x;            // 0..7
    const int bm = blockIdx.y;            // 0..511
    const int wm = wid & 1;
    const int wn = wid >> 1;

    uint32_t soff[8];
    const uint4* gptr[8];
#pragma unroll
    for (int j = 0; j < 8; j++) {
        int c = tid + j * 256;
        int cl   = c & 31;
        int blk  = (c >> 5) & 7;
        int term = (c >> 8) & 1;
        int kb   = (c >> 9) & 1;
        if (c < 1024) {
            int rb = bm * 8 + blk;
            gptr[j] = g_A2 + (((size_t)(rb * 64 + kb) * 2 + term) * 32 + cl);
        } else {
            int nb = bn * 8 + blk;
            gptr[j] = g_W2 + (((size_t)(nb * 64 + kb) * 2 + term) * 32 + cl);
        }
        soff[j] = (uint32_t)(c * 16);
    }

    float acc[4][4][4];
#pragma unroll
    for (int a = 0; a < 4; a++)
#pragma unroll
        for (int b = 0; b < 4; b++)
#pragma unroll
            for (int d = 0; d < 4; d++) acc[a][b][d] = 0.f;

#pragma unroll
    for (int s = 0; s < 2; s++) {
#pragma unroll
        for (int j = 0; j < 8; j++)
            CP_ASYNC16(sbase + s * STAGE_BYTES + soff[j], gptr[j] + (size_t)s * 128);
        CP_COMMIT();
    }

    const int mbB = wm * 4;
    const int nbB = wn * 2;

    for (int i = 0; i < 32; i++) {
        CP_WAIT1();
        __syncthreads();

        if (i + 2 < 32) {
            uint32_t sb = sbase + ((i + 2) % N_STAGES) * STAGE_BYTES;
#pragma unroll
            for (int j = 0; j < 8; j++)
                CP_ASYNC16(sb + soff[j], gptr[j] + (size_t)(i + 2) * 128);
        }
        CP_COMMIT();

        const uint32_t st = sbase + (i % N_STAGES) * STAGE_BYTES;
#pragma unroll
        for (int kb = 0; kb < 2; kb++) {
            uint4 ah[4], al[4], bh[2], bl[2];
#pragma unroll
            for (int mb = 0; mb < 4; mb++) {
                uint32_t ahi = st + ((kb * 2 + 0) * 8 + mbB + mb) * 512 + lane * 16;
                uint32_t alo = st + ((kb * 2 + 1) * 8 + mbB + mb) * 512 + lane * 16;
                LDS128(ah[mb], ahi);
                LDS128(al[mb], alo);
            }
#pragma unroll
            for (int p = 0; p < 2; p++) {
                uint32_t bhi = st + 16384 + ((kb * 2 + 0) * 8 + nbB + p) * 512 + lane * 16;
                uint32_t blo = st + 16384 + ((kb * 2 + 1) * 8 + nbB + p) * 512 + lane * 16;
                LDS128(bh[p], bhi);
                LDS128(bl[p], blo);
            }
#pragma unroll
            for (int term = 0; term < 3; term++) {
#pragma unroll
                for (int mt = 0; mt < 4; mt++) {
#pragma unroll
                    for (int nt = 0; nt < 4; nt++) {
                        const uint4& A = (term == 2) ? al[mt] : ah[mt];
                        const uint4& B = (term == 1) ? bl[nt >> 1] : bh[nt >> 1];
                        uint32_t b0 = (nt & 1) ? B.z : B.x;
                        uint32_t b1 = (nt & 1) ? B.w : B.y;
                        mma16816(acc[mt][nt], A, b0, b1);
                    }
                }
            }
        }
    }

    // ---- tail: drain pipeline, then reuse smem for staging ----
    CP_WAIT0();
    __syncthreads();

    const uint32_t tauT = sbase;                  // [128][68] float
    const uint32_t fT   = sbase + 128 * TPAD * 4; // [128][68] float
    const int g  = lane >> 2;
    const int tg = lane & 3;

    // Phase 1: scatter raw pre-activations to smem
#pragma unroll
    for (int mt = 0; mt < 4; mt++) {
        int r0 = wm * 64 + mt * 16 + g;
        int r1 = r0 + 8;
#pragma unroll
        for (int nt = 0; nt < 4; nt++) {
            int jj = wn * 16 + nt * 4 + tg;
            asm volatile("st.shared.f32 [%0], %1;" :: "r"(tauT + (uint32_t)(r0 * TPAD + jj) * 4), "f"(acc[mt][nt][0]) : "memory");
            asm volatile("st.shared.f32 [%0], %1;" :: "r"(fT   + (uint32_t)(r0 * TPAD + jj) * 4), "f"(acc[mt][nt][1]) : "memory");
            asm volatile("st.shared.f32 [%0], %1;" :: "r"(tauT + (uint32_t)(r1 * TPAD + jj) * 4), "f"(acc[mt][nt][2]) : "memory");
            asm volatile("st.shared.f32 [%0], %1;" :: "r"(fT   + (uint32_t)(r1 * TPAD + jj) * 4), "f"(acc[mt][nt][3]) : "memory");
        }
    }
    __syncthreads();

    // Phase 2: coalesced writeout, h prefetched in batches of 4 (MLP=4).
    const int jj4 = tid & 15;
    const int rgrp = tid >> 4;
    const int jbase = bn * 64;
    const float4 bt4 = ((const float4*)b_tau)[jbase / 4 + jj4];
    const float4 bi4 = ((const float4*)b_in)[jbase / 4 + jj4];

#pragma unroll
    for (int half = 0; half < 2; half++) {
        float4 h4s[4];
#pragma unroll
        for (int u = 0; u < 4; u++) {
            int r = rgrp + (half * 4 + u) * 16;
            size_t row = (size_t)bm * 128 + r;
            h4s[u] = *((const float4*)(hin + row * H_DIM + jbase) + jj4);
        }
#pragma unroll
        for (int u = 0; u < 4; u++) {
            int r = rgrp + (half * 4 + u) * 16;
            size_t row = (size_t)bm * 128 + r;

            float4 tp, fp;
            LDS128(*(uint4*)&tp, tauT + (uint32_t)(r * TPAD + jj4 * 4) * 4);
            LDS128(*(uint4*)&fp, fT   + (uint32_t)(r * TPAD + jj4 * 4) * 4);
            float4 h4 = h4s[u];

            float4 tv, yv;
            float s = 0.f, q = 0.f;
            {
                const float* ptp = &tp.x; const float* pfp = &fp.x;
                const float* ph = &h4.x; const float* pbt = &bt4.x; const float* pbi = &bi4.x;
                float* ptv = &tv.x; float* pyv = &yv.x;
#pragma unroll
                for (int c = 0; c < 4; c++) {
                    float tau = 0.5f + 4.5f / (1.0f + __expf(-(ptp[c] + pbt[c])));
                    float f   = tanhf(pfp[c] + pbi[c]);
                    float yy  = ph[c] + 0.1f * (f - ph[c]) / tau;
                    ptv[c] = tau; pyv[c] = yy;
                    s += yy; q += yy * yy;
                }
            }
            *((float4*)(out_tau + row * H_DIM + jbase) + jj4) = tv;
            *((float4*)(g_Y + row * H_DIM + jbase) + jj4) = yv;

            s += __shfl_xor_sync(0xffffffffu, s, 1);
            q += __shfl_xor_sync(0xffffffffu, q, 1);
            s += __shfl_xor_sync(0xffffffffu, s, 2);
            q += __shfl_xor_sync(0xffffffffu, q, 2);
            s += __shfl_xor_sync(0xffffffffu, s, 4);
            q += __shfl_xor_sync(0xffffffffu, q, 4);
            s += __shfl_xor_sync(0xffffffffu, s, 8);
            q += __shfl_xor_sync(0xffffffffu, q, 8);
            if (jj4 == 0)
                g_Spart[row * 8 + bn] = make_float2(s, q);
        }
    }
}

// ---------------------------------------------------------------------------
// Finalize (verbatim): 4 rows/block, 2 float4/thread, y-loads early.
// ---------------------------------------------------------------------------
__global__ __launch_bounds__(256)
void finalize_kernel(const float* __restrict__ gamma, const float* __restrict__ beta,
                     float* __restrict__ out_h) {
    const int tid = threadIdx.x;
    const size_t row0 = (size_t)blockIdx.x * 4;
    const int r = tid >> 6;
    const int t = tid & 63;
    const size_t row = row0 + r;

    float4 ya = *((const float4*)(g_Y + row * H_DIM) + t);
    float4 yb = *((const float4*)(g_Y + row * H_DIM) + t + 64);

    __shared__ float2 mv[4];
    if (tid < 32) {
        int rr = tid >> 3, part = tid & 7;
        float2 p = g_Spart[(row0 + rr) * 8 + part];
        float s = p.x, q = p.y;
        s += __shfl_xor_sync(0xffffffffu, s, 1);
        q += __shfl_xor_sync(0xffffffffu, q, 1);
        s += __shfl_xor_sync(0xffffffffu, s, 2);
        q += __shfl_xor_sync(0xffffffffu, q, 2);
        s += __shfl_xor_sync(0xffffffffu, s, 4);
        q += __shfl_xor_sync(0xffffffffu, q, 4);
        if (part == 0) {
            float mu  = s * (1.0f / H_DIM);
            float var = q * (1.0f / H_DIM) - mu * mu;
            mv[rr] = make_float2(mu, rsqrtf(var + 1e-5f));
        }
    }
    __syncthreads();

    float mu  = mv[r].x;
    float inv = mv[r].y;

    float4 ga = ((const float4*)gamma)[t];
    float4 gb = ((const float4*)gamma)[t + 64];
    float4 ba = ((const float4*)beta)[t];
    float4 bb = ((const float4*)beta)[t + 64];

    float4 oa, ob;
    oa.x = (ya.x - mu) * inv * ga.x + ba.x;
    oa.y = (ya.y - mu) * inv * ga.y + ba.y;
    oa.z = (ya.z - mu) * inv * ga.z + ba.z;
    oa.w = (ya.w - mu) * inv * ga.w + ba.w;
    ob.x = (yb.x - mu) * inv * gb.x + bb.x;
    ob.y = (yb.y - mu) * inv * gb.y + bb.y;
    ob.z = (yb.z - mu) * inv * gb.z + bb.z;
    ob.w = (yb.w - mu) * inv * gb.w + bb.w;

    *((float4*)(out_h + row * H_DIM) + t) = oa;
    *((float4*)(out_h + row * H_DIM) + t + 64) = ob;
}

// ---------------------------------------------------------------------------
extern "C" void kernel_launch(void* const* d_in, const int* in_sizes, int n_in,
                              void* d_out, int out_size) {
    const float* x     = (const float*)d_in[0];
    const float* h     = (const float*)d_in[1];
    const float* W_in  = (const float*)d_in[2];
    const float* b_in  = (const float*)d_in[3];
    const float* W_rec = (const float*)d_in[4];
    const float* W_tau = (const float*)d_in[5];
    const float* b_tau = (const float*)d_in[6];
    const float* gamma = (const float*)d_in[7];
    const float* beta  = (const float*)d_in[8];

    const int B = in_sizes[0] / I_DIM;    // 65536

    float* out = (float*)d_out;
    float* out_h   = out;
    float* out_tau = out + (size_t)B * H_DIM;

    prep_kernel<<<B / 16 + 512, 256>>>(x, h, W_in, W_rec, W_tau);

    cudaFuncSetAttribute(gemm_mma_kernel,
                         cudaFuncAttributeMaxDynamicSharedMemorySize,
                         N_STAGES * STAGE_BYTES);
    dim3 ggrid(NTOT / 128, B / 128);      // (8, 512)
    gemm_mma_kernel<<<ggrid, 256, N_STAGES * STAGE_BYTES>>>(h, b_in, b_tau, out_tau);

    finalize_kernel<<<B / 4, 256>>>(gamma, beta, out_h);
}

// round 15
// speedup vs baseline: 2.1029x; 1.9912x over previous
#include <cuda_runtime.h>
#include <cuda_fp16.h>
#include <cstdint>
#include <cmath>

#define I_DIM 512
#define H_DIM 512
#define KTOT  1024
#define NTOT  1024
#define BATCH 65536

// ---------------------------------------------------------------------------
// Device scratch (fp16 single-term operands)
// A2h: u4 index = (rb*64 + kb)*32 + lane      rb: 16-row block, kb: k16 block
// W2h: u4 index = (nb*64 + kb)*32 + lane      nb: 16-col block
// Column interleave on W (2j=tau, 2j+1=f); k-permutation pi on both:
//   tile positions (2q,2q+1,2q+8,2q+9) <- global k = kb*16 + (4q..4q+3)
// ---------------------------------------------------------------------------
__device__ uint4  g_A2h[(size_t)4096 * 64 * 32];         // 134 MB
__device__ uint4  g_W2h[(size_t)64 * 64 * 32];           // 2 MB
__device__ float  g_Y[(size_t)BATCH * H_DIM];            // 128 MB (pre-LN y)
__device__ float2 g_Spart[(size_t)BATCH * 8];            // 4 MB (LN partials, per bn)

__device__ __forceinline__ uint32_t smem_u32(const void* p) {
    uint32_t a;
    asm("{ .reg .u64 t; cvta.to.shared.u64 t, %1; cvt.u32.u64 %0, t; }"
        : "=r"(a) : "l"(p));
    return a;
}
__device__ __forceinline__ uint32_t pack_h2(float a, float b) {
    __half2 h = __floats2half2_rn(a, b);     // a -> low, b -> high
    return *(uint32_t*)&h;
}
__device__ __forceinline__ void mma16816_f16(float* c, const uint4& a,
                                             uint32_t b0, uint32_t b1) {
    asm volatile(
        "mma.sync.aligned.m16n8k16.row.col.f32.f16.f16.f32 "
        "{%0,%1,%2,%3}, {%4,%5,%6,%7}, {%8,%9}, {%0,%1,%2,%3};"
        : "+f"(c[0]), "+f"(c[1]), "+f"(c[2]), "+f"(c[3])
        : "r"(a.x), "r"(a.y), "r"(a.z), "r"(a.w), "r"(b0), "r"(b1));
}
#define CP_ASYNC16(dst, src) \
    asm volatile("cp.async.cg.shared.global [%0], [%1], 16;" \
                 :: "r"(dst), "l"(src) : "memory")
#define CP_COMMIT() asm volatile("cp.async.commit_group;" ::: "memory")
#define CP_WAIT1()  asm volatile("cp.async.wait_group 1;" ::: "memory")
#define CP_WAIT0()  asm volatile("cp.async.wait_group 0;" ::: "memory")
#define LDS128(v, addr) \
    asm volatile("ld.shared.v4.u32 {%0,%1,%2,%3}, [%4];" \
        : "=r"((v).x), "=r"((v).y), "=r"((v).z), "=r"((v).w) : "r"(addr))

// ---------------------------------------------------------------------------
// W element fetch (interleaved columns: packed col c -> j=c>>1; even=tau, odd=f).
// ---------------------------------------------------------------------------
__device__ __forceinline__ float w_at2(const float* W_in, const float* W_rec,
                                       const float* W_tau, int c, int k) {
    int j = c >> 1;
    if ((c & 1) == 0) return W_tau[j * KTOT + k];
    return (k < I_DIM) ? W_in[j * I_DIM + k] : W_rec[j * H_DIM + (k - I_DIM)];
}

// ---------------------------------------------------------------------------
// Combined prep kernel (fp16, pi on both A and W):
//   blocks 0..4095   : convert A = [x|h] to fragment-linear fp16 tiles
//   blocks 4096..4607: pack W to fragment-linear fp16 tiles
// ---------------------------------------------------------------------------
__global__ __launch_bounds__(256)
void prep_kernel(const float* __restrict__ x, const float* __restrict__ h,
                 const float* __restrict__ W_in, const float* __restrict__ W_rec,
                 const float* __restrict__ W_tau) {
    const int tid = threadIdx.x;
    const int lane = tid & 31;

    if (blockIdx.x < 4096) {
        const int rb = blockIdx.x;
        const int wid = tid >> 5;

        const int r0 = lane >> 2;
        const int tg4 = (lane & 3) * 4;
        const size_t rowA = (size_t)rb * 16 + r0;
        const size_t rowB = rowA + 8;

#pragma unroll
        for (int j = 0; j < 8; j++) {
            int kb = wid * 8 + j;
            int kg = kb * 16 + tg4;
            const float* srcA;
            const float* srcB;
            if (kb < 32) { srcA = x + rowA * I_DIM + kg;          srcB = x + rowB * I_DIM + kg; }
            else         { srcA = h + rowA * H_DIM + (kg - 512);  srcB = h + rowB * H_DIM + (kg - 512); }

            float4 va = *(const float4*)srcA;
            float4 vb = *(const float4*)srcB;

            uint4 hi;
            hi.x = pack_h2(va.x, va.y); hi.y = pack_h2(vb.x, vb.y);
            hi.z = pack_h2(va.z, va.w); hi.w = pack_h2(vb.z, vb.w);

            g_A2h[(size_t)(rb * 64 + kb) * 32 + lane] = hi;
        }
    } else {
        int t = (blockIdx.x - 4096) * blockDim.x + tid;
        int idx = t >> 5;
        int kb = idx & 63;
        int nb = idx >> 6;

        int n0 = nb * 16 + (lane >> 2);
        int k0 = kb * 16 + (lane & 3) * 4;

        float v[8];
        v[0] = w_at2(W_in, W_rec, W_tau, n0,     k0);
        v[1] = w_at2(W_in, W_rec, W_tau, n0,     k0 + 1);
        v[2] = w_at2(W_in, W_rec, W_tau, n0,     k0 + 2);
        v[3] = w_at2(W_in, W_rec, W_tau, n0,     k0 + 3);
        v[4] = w_at2(W_in, W_rec, W_tau, n0 + 8, k0);
        v[5] = w_at2(W_in, W_rec, W_tau, n0 + 8, k0 + 1);
        v[6] = w_at2(W_in, W_rec, W_tau, n0 + 8, k0 + 2);
        v[7] = w_at2(W_in, W_rec, W_tau, n0 + 8, k0 + 3);

        uint4 hi;
        hi.x = pack_h2(v[0], v[1]); hi.y = pack_h2(v[2], v[3]);
        hi.z = pack_h2(v[4], v[5]); hi.w = pack_h2(v[6], v[7]);

        g_W2h[(size_t)(nb * 64 + kb) * 32 + lane] = hi;
    }
}

// ---------------------------------------------------------------------------
// fp16 GEMM + smem-staged fused epilogue.
// CTA 128x128, warp 64x32 (2x4), BK=32, 3-stage cp.async (16KB stages).
// Stage: A fp16 @0 (8KB: (kb*8+mb)*512 + lane*16), B fp16 @8192 (8KB).
// Tail identical to R14 (smem-staged, coalesced, LN partials per (row,bn)).
// ---------------------------------------------------------------------------
#define STAGE_BYTES 16384
#define N_STAGES 3
#define TPAD 68
#define SMEM_REQ (2 * 128 * TPAD * 4)   // 69632 B (tail dominates; loop uses 48KB)

__global__ __launch_bounds__(256)
void gemm_mma_kernel(const float* __restrict__ hin,
                     const float* __restrict__ b_in,
                     const float* __restrict__ b_tau,
                     float* __restrict__ out_tau) {
    extern __shared__ char smem[];
    const uint32_t sbase = smem_u32(smem);

    const int tid  = threadIdx.x;
    const int wid  = tid >> 5;
    const int lane = tid & 31;
    const int bn = blockIdx.x;            // 0..7
    const int bm = blockIdx.y;            // 0..511
    const int wm = wid & 1;
    const int wn = wid >> 1;

    // 1024 chunks/stage, 4 per thread
    uint32_t soff[4];
    const uint4* gptr[4];
#pragma unroll
    for (int j = 0; j < 4; j++) {
        int c = tid + j * 256;
        if (c < 512) {
            int cl = c & 31;
            int mb = (c >> 5) & 7;
            int kb = (c >> 8) & 1;
            int rb = bm * 8 + mb;
            gptr[j] = g_A2h + ((size_t)(rb * 64 + kb) * 32 + cl);
            soff[j] = (uint32_t)(c * 16);
        } else {
            int cb = c - 512;
            int cl = cb & 31;
            int nb = (cb >> 5) & 7;
            int kb = (cb >> 8) & 1;
            int nbg = bn * 8 + nb;
            gptr[j] = g_W2h + ((size_t)(nbg * 64 + kb) * 32 + cl);
            soff[j] = (uint32_t)(8192 + cb * 16);
        }
    }

    float acc[4][4][4];
#pragma unroll
    for (int a = 0; a < 4; a++)
#pragma unroll
        for (int b = 0; b < 4; b++)
#pragma unroll
            for (int d = 0; d < 4; d++) acc[a][b][d] = 0.f;

    // prologue: stages 0,1 (advance 64 u4 per iter)
#pragma unroll
    for (int s = 0; s < 2; s++) {
#pragma unroll
        for (int j = 0; j < 4; j++)
            CP_ASYNC16(sbase + s * STAGE_BYTES + soff[j], gptr[j] + (size_t)s * 64);
        CP_COMMIT();
    }

    const int mbB = wm * 4;
    const int nbB = wn * 2;

    for (int i = 0; i < 32; i++) {
        CP_WAIT1();
        __syncthreads();

        if (i + 2 < 32) {
            uint32_t sb = sbase + ((i + 2) % N_STAGES) * STAGE_BYTES;
#pragma unroll
            for (int j = 0; j < 4; j++)
                CP_ASYNC16(sb + soff[j], gptr[j] + (size_t)(i + 2) * 64);
        }
        CP_COMMIT();

        const uint32_t st = sbase + (i % N_STAGES) * STAGE_BYTES;
#pragma unroll
        for (int kb = 0; kb < 2; kb++) {
            uint4 ah[4], bh[2];
#pragma unroll
            for (int mt = 0; mt < 4; mt++) {
                int mb = mbB + mt;
                LDS128(ah[mt], st + (uint32_t)((kb * 8 + mb) * 512) + lane * 16);
            }
#pragma unroll
            for (int p = 0; p < 2; p++) {
                int nb = nbB + p;
                LDS128(bh[p], st + (uint32_t)(8192 + (kb * 8 + nb) * 512) + lane * 16);
            }
#pragma unroll
            for (int mt = 0; mt < 4; mt++) {
#pragma unroll
                for (int nt = 0; nt < 4; nt++) {
                    const uint4& B = bh[nt >> 1];
                    uint32_t b0 = (nt & 1) ? B.z : B.x;
                    uint32_t b1 = (nt & 1) ? B.w : B.y;
                    mma16816_f16(acc[mt][nt], ah[mt], b0, b1);
                }
            }
        }
    }

    // ---- tail: drain pipeline, then reuse smem for staging ----
    CP_WAIT0();
    __syncthreads();

    const uint32_t tauT = sbase;                  // [128][68] float
    const uint32_t fT   = sbase + 128 * TPAD * 4; // [128][68] float
    const int g  = lane >> 2;
    const int tg = lane & 3;

    // Phase 1: scatter raw pre-activations to smem
#pragma unroll
    for (int mt = 0; mt < 4; mt++) {
        int r0 = wm * 64 + mt * 16 + g;
        int r1 = r0 + 8;
#pragma unroll
        for (int nt = 0; nt < 4; nt++) {
            int jj = wn * 16 + nt * 4 + tg;
            asm volatile("st.shared.f32 [%0], %1;" :: "r"(tauT + (uint32_t)(r0 * TPAD + jj) * 4), "f"(acc[mt][nt][0]) : "memory");
            asm volatile("st.shared.f32 [%0], %1;" :: "r"(fT   + (uint32_t)(r0 * TPAD + jj) * 4), "f"(acc[mt][nt][1]) : "memory");
            asm volatile("st.shared.f32 [%0], %1;" :: "r"(tauT + (uint32_t)(r1 * TPAD + jj) * 4), "f"(acc[mt][nt][2]) : "memory");
            asm volatile("st.shared.f32 [%0], %1;" :: "r"(fT   + (uint32_t)(r1 * TPAD + jj) * 4), "f"(acc[mt][nt][3]) : "memory");
        }
    }
    __syncthreads();

    // Phase 2: coalesced writeout, h prefetched in batches of 4 (MLP=4).
    const int jj4 = tid & 15;
    const int rgrp = tid >> 4;
    const int jbase = bn * 64;
    const float4 bt4 = ((const float4*)b_tau)[jbase / 4 + jj4];
    const float4 bi4 = ((const float4*)b_in)[jbase / 4 + jj4];

#pragma unroll
    for (int half = 0; half < 2; half++) {
        float4 h4s[4];
#pragma unroll
        for (int u = 0; u < 4; u++) {
            int r = rgrp + (half * 4 + u) * 16;
            size_t row = (size_t)bm * 128 + r;
            h4s[u] = *((const float4*)(hin + row * H_DIM + jbase) + jj4);
        }
#pragma unroll
        for (int u = 0; u < 4; u++) {
            int r = rgrp + (half * 4 + u) * 16;
            size_t row = (size_t)bm * 128 + r;

            float4 tp, fp;
            LDS128(*(uint4*)&tp, tauT + (uint32_t)(r * TPAD + jj4 * 4) * 4);
            LDS128(*(uint4*)&fp, fT   + (uint32_t)(r * TPAD + jj4 * 4) * 4);
            float4 h4 = h4s[u];

            float4 tv, yv;
            float s = 0.f, q = 0.f;
            {
                const float* ptp = &tp.x; const float* pfp = &fp.x;
                const float* ph = &h4.x; const float* pbt = &bt4.x; const float* pbi = &bi4.x;
                float* ptv = &tv.x; float* pyv = &yv.x;
#pragma unroll
                for (int c = 0; c < 4; c++) {
                    float tau = 0.5f + 4.5f / (1.0f + __expf(-(ptp[c] + pbt[c])));
                    float f   = tanhf(pfp[c] + pbi[c]);
                    float yy  = ph[c] + 0.1f * (f - ph[c]) / tau;
                    ptv[c] = tau; pyv[c] = yy;
                    s += yy; q += yy * yy;
                }
            }
            *((float4*)(out_tau + row * H_DIM + jbase) + jj4) = tv;
            *((float4*)(g_Y + row * H_DIM + jbase) + jj4) = yv;

            s += __shfl_xor_sync(0xffffffffu, s, 1);
            q += __shfl_xor_sync(0xffffffffu, q, 1);
            s += __shfl_xor_sync(0xffffffffu, s, 2);
            q += __shfl_xor_sync(0xffffffffu, q, 2);
            s += __shfl_xor_sync(0xffffffffu, s, 4);
            q += __shfl_xor_sync(0xffffffffu, q, 4);
            s += __shfl_xor_sync(0xffffffffu, s, 8);
            q += __shfl_xor_sync(0xffffffffu, q, 8);
            if (jj4 == 0)
                g_Spart[row * 8 + bn] = make_float2(s, q);
        }
    }
}

// ---------------------------------------------------------------------------
// Finalize (verbatim): 4 rows/block, 2 float4/thread, y-loads early.
// ---------------------------------------------------------------------------
__global__ __launch_bounds__(256)
void finalize_kernel(const float* __restrict__ gamma, const float* __restrict__ beta,
                     float* __restrict__ out_h) {
    const int tid = threadIdx.x;
    const size_t row0 = (size_t)blockIdx.x * 4;
    const int r = tid >> 6;
    const int t = tid & 63;
    const size_t row = row0 + r;

    float4 ya = *((const float4*)(g_Y + row * H_DIM) + t);
    float4 yb = *((const float4*)(g_Y + row * H_DIM) + t + 64);

    __shared__ float2 mv[4];
    if (tid < 32) {
        int rr = tid >> 3, part = tid & 7;
        float2 p = g_Spart[(row0 + rr) * 8 + part];
        float s = p.x, q = p.y;
        s += __shfl_xor_sync(0xffffffffu, s, 1);
        q += __shfl_xor_sync(0xffffffffu, q, 1);
        s += __shfl_xor_sync(0xffffffffu, s, 2);
        q += __shfl_xor_sync(0xffffffffu, q, 2);
        s += __shfl_xor_sync(0xffffffffu, s, 4);
        q += __shfl_xor_sync(0xffffffffu, q, 4);
        if (part == 0) {
            float mu  = s * (1.0f / H_DIM);
            float var = q * (1.0f / H_DIM) - mu * mu;
            mv[rr] = make_float2(mu, rsqrtf(var + 1e-5f));
        }
    }
    __syncthreads();

    float mu  = mv[r].x;
    float inv = mv[r].y;

    float4 ga = ((const float4*)gamma)[t];
    float4 gb = ((const float4*)gamma)[t + 64];
    float4 ba = ((const float4*)beta)[t];
    float4 bb = ((const float4*)beta)[t + 64];

    float4 oa, ob;
    oa.x = (ya.x - mu) * inv * ga.x + ba.x;
    oa.y = (ya.y - mu) * inv * ga.y + ba.y;
    oa.z = (ya.z - mu) * inv * ga.z + ba.z;
    oa.w = (ya.w - mu) * inv * ga.w + ba.w;
    ob.x = (yb.x - mu) * inv * gb.x + bb.x;
    ob.y = (yb.y - mu) * inv * gb.y + bb.y;
    ob.z = (yb.z - mu) * inv * gb.z + bb.z;
    ob.w = (yb.w - mu) * inv * gb.w + bb.w;

    *((float4*)(out_h + row * H_DIM) + t) = oa;
    *((float4*)(out_h + row * H_DIM) + t + 64) = ob;
}

// ---------------------------------------------------------------------------
extern "C" void kernel_launch(void* const* d_in, const int* in_sizes, int n_in,
                              void* d_out, int out_size) {
    const float* x     = (const float*)d_in[0];
    const float* h     = (const float*)d_in[1];
    const float* W_in  = (const float*)d_in[2];
    const float* b_in  = (const float*)d_in[3];
    const float* W_rec = (const float*)d_in[4];
    const float* W_tau = (const float*)d_in[5];
    const float* b_tau = (const float*)d_in[6];
    const float* gamma = (const float*)d_in[7];
    const float* beta  = (const float*)d_in[8];

    const int B = in_sizes[0] / I_DIM;    // 65536

    float* out = (float*)d_out;
    float* out_h   = out;
    float* out_tau = out + (size_t)B * H_DIM;

    prep_kernel<<<B / 16 + 512, 256>>>(x, h, W_in, W_rec, W_tau);

    cudaFuncSetAttribute(gemm_mma_kernel,
                         cudaFuncAttributeMaxDynamicSharedMemorySize, SMEM_REQ);
    dim3 ggrid(NTOT / 128, B / 128);      // (8, 512)
    gemm_mma_kernel<<<ggrid, 256, SMEM_REQ>>>(h, b_in, b_tau, out_tau);

    finalize_kernel<<<B / 4, 256>>>(gamma, beta, out_h);
}

// round 16
// speedup vs baseline: 2.1747x; 1.0342x over previous
#include <cuda_runtime.h>
#include <cuda_fp16.h>
#include <cstdint>
#include <cmath>

#define I_DIM 512
#define H_DIM 512
#define KTOT  1024
#define NTOT  1024
#define BATCH 65536

// ---------------------------------------------------------------------------
// Device scratch (fp16 single-term operands)
// A2h: u4 index = (rb*64 + kb)*32 + lane      rb: 16-row block, kb: k16 block
// W2h: u4 index = (nb*64 + kb)*32 + lane      nb: 16-col block
// Column interleave on W (2j=tau, 2j+1=f); k-permutation pi on both.
// ---------------------------------------------------------------------------
__device__ uint4  g_A2h[(size_t)4096 * 64 * 32];         // 134 MB
__device__ uint4  g_W2h[(size_t)64 * 64 * 32];           // 2 MB
__device__ float  g_Y[(size_t)BATCH * H_DIM];            // 128 MB (pre-LN y)
__device__ float2 g_Spart[(size_t)BATCH * 8];            // 4 MB (LN partials, per bn)

__device__ __forceinline__ uint32_t smem_u32(const void* p) {
    uint32_t a;
    asm("{ .reg .u64 t; cvta.to.shared.u64 t, %1; cvt.u32.u64 %0, t; }"
        : "=r"(a) : "l"(p));
    return a;
}
__device__ __forceinline__ uint32_t pack_h2(float a, float b) {
    __half2 h = __floats2half2_rn(a, b);
    return *(uint32_t*)&h;
}
__device__ __forceinline__ void mma16816_f16(float* c, const uint4& a,
                                             uint32_t b0, uint32_t b1) {
    asm volatile(
        "mma.sync.aligned.m16n8k16.row.col.f32.f16.f16.f32 "
        "{%0,%1,%2,%3}, {%4,%5,%6,%7}, {%8,%9}, {%0,%1,%2,%3};"
        : "+f"(c[0]), "+f"(c[1]), "+f"(c[2]), "+f"(c[3])
        : "r"(a.x), "r"(a.y), "r"(a.z), "r"(a.w), "r"(b0), "r"(b1));
}
#define CP_ASYNC16(dst, src) \
    asm volatile("cp.async.cg.shared.global [%0], [%1], 16;" \
                 :: "r"(dst), "l"(src) : "memory")
#define CP_COMMIT() asm volatile("cp.async.commit_group;" ::: "memory")
#define CP_WAIT2()  asm volatile("cp.async.wait_group 2;" ::: "memory")
#define CP_WAIT0()  asm volatile("cp.async.wait_group 0;" ::: "memory")
#define LDS128(v, addr) \
    asm volatile("ld.shared.v4.u32 {%0,%1,%2,%3}, [%4];" \
        : "=r"((v).x), "=r"((v).y), "=r"((v).z), "=r"((v).w) : "r"(addr))

// ---------------------------------------------------------------------------
__device__ __forceinline__ float w_at2(const float* W_in, const float* W_rec,
                                       const float* W_tau, int c, int k) {
    int j = c >> 1;
    if ((c & 1) == 0) return W_tau[j * KTOT + k];
    return (k < I_DIM) ? W_in[j * I_DIM + k] : W_rec[j * H_DIM + (k - I_DIM)];
}

// ---------------------------------------------------------------------------
// Combined prep kernel (fp16, pi on both A and W) — unchanged from R15.
// ---------------------------------------------------------------------------
__global__ __launch_bounds__(256)
void prep_kernel(const float* __restrict__ x, const float* __restrict__ h,
                 const float* __restrict__ W_in, const float* __restrict__ W_rec,
                 const float* __restrict__ W_tau) {
    const int tid = threadIdx.x;
    const int lane = tid & 31;

    if (blockIdx.x < 4096) {
        const int rb = blockIdx.x;
        const int wid = tid >> 5;

        const int r0 = lane >> 2;
        const int tg4 = (lane & 3) * 4;
        const size_t rowA = (size_t)rb * 16 + r0;
        const size_t rowB = rowA + 8;

#pragma unroll
        for (int j = 0; j < 8; j++) {
            int kb = wid * 8 + j;
            int kg = kb * 16 + tg4;
            const float* srcA;
            const float* srcB;
            if (kb < 32) { srcA = x + rowA * I_DIM + kg;          srcB = x + rowB * I_DIM + kg; }
            else         { srcA = h + rowA * H_DIM + (kg - 512);  srcB = h + rowB * H_DIM + (kg - 512); }

            float4 va = *(const float4*)srcA;
            float4 vb = *(const float4*)srcB;

            uint4 hi;
            hi.x = pack_h2(va.x, va.y); hi.y = pack_h2(vb.x, vb.y);
            hi.z = pack_h2(va.z, va.w); hi.w = pack_h2(vb.z, vb.w);

            g_A2h[(size_t)(rb * 64 + kb) * 32 + lane] = hi;
        }
    } else {
        int t = (blockIdx.x - 4096) * blockDim.x + tid;
        int idx = t >> 5;
        int kb = idx & 63;
        int nb = idx >> 6;

        int n0 = nb * 16 + (lane >> 2);
        int k0 = kb * 16 + (lane & 3) * 4;

        float v[8];
        v[0] = w_at2(W_in, W_rec, W_tau, n0,     k0);
        v[1] = w_at2(W_in, W_rec, W_tau, n0,     k0 + 1);
        v[2] = w_at2(W_in, W_rec, W_tau, n0,     k0 + 2);
        v[3] = w_at2(W_in, W_rec, W_tau, n0,     k0 + 3);
        v[4] = w_at2(W_in, W_rec, W_tau, n0 + 8, k0);
        v[5] = w_at2(W_in, W_rec, W_tau, n0 + 8, k0 + 1);
        v[6] = w_at2(W_in, W_rec, W_tau, n0 + 8, k0 + 2);
        v[7] = w_at2(W_in, W_rec, W_tau, n0 + 8, k0 + 3);

        uint4 hi;
        hi.x = pack_h2(v[0], v[1]); hi.y = pack_h2(v[2], v[3]);
        hi.z = pack_h2(v[4], v[5]); hi.w = pack_h2(v[6], v[7]);

        g_W2h[(size_t)(nb * 64 + kb) * 32 + lane] = hi;
    }
}

// ---------------------------------------------------------------------------
// fp16 GEMM + smem-staged fused epilogue.
// CTA 128x128, 4 warps, warp tile 64x64 (2x2), BK=32, 4-stage cp.async (16KB).
// Stage: A fp16 @0 (8KB: (kb*8+mb)*512 + lane*16), B fp16 @8192 (8KB).
// ---------------------------------------------------------------------------
#define STAGE_BYTES 16384
#define N_STAGES 4
#define TPAD 68
#define SMEM_REQ (2 * 128 * TPAD * 4)   // 69632 B (tail dominates; loop uses 64KB)

__global__ __launch_bounds__(128)
void gemm_mma_kernel(const float* __restrict__ hin,
                     const float* __restrict__ b_in,
                     const float* __restrict__ b_tau,
                     float* __restrict__ out_tau) {
    extern __shared__ char smem[];
    const uint32_t sbase = smem_u32(smem);

    const int tid  = threadIdx.x;
    const int wid  = tid >> 5;            // 0..3
    const int lane = tid & 31;
    const int bn = blockIdx.x;            // 0..7
    const int bm = blockIdx.y;            // 0..511
    const int wm = wid & 1;
    const int wn = wid >> 1;              // 0..1

    // 1024 chunks/stage, 8 per thread (128 threads)
    uint32_t soff[8];
    const uint4* gptr[8];
#pragma unroll
    for (int j = 0; j < 8; j++) {
        int c = tid + j * 128;
        if (c < 512) {
            int cl = c & 31;
            int mb = (c >> 5) & 7;
            int kb = (c >> 8) & 1;
            int rb = bm * 8 + mb;
            gptr[j] = g_A2h + ((size_t)(rb * 64 + kb) * 32 + cl);
            soff[j] = (uint32_t)(c * 16);
        } else {
            int cb = c - 512;
            int cl = cb & 31;
            int nb = (cb >> 5) & 7;
            int kb = (cb >> 8) & 1;
            int nbg = bn * 8 + nb;
            gptr[j] = g_W2h + ((size_t)(nbg * 64 + kb) * 32 + cl);
            soff[j] = (uint32_t)(8192 + cb * 16);
        }
    }

    float acc[4][8][4];
#pragma unroll
    for (int a = 0; a < 4; a++)
#pragma unroll
        for (int b = 0; b < 8; b++)
#pragma unroll
            for (int d = 0; d < 4; d++) acc[a][b][d] = 0.f;

    // prologue: stages 0,1,2 (advance 64 u4 per iter)
#pragma unroll
    for (int s = 0; s < 3; s++) {
#pragma unroll
        for (int j = 0; j < 8; j++)
            CP_ASYNC16(sbase + s * STAGE_BYTES + soff[j], gptr[j] + (size_t)s * 64);
        CP_COMMIT();
    }

    const int mbB = wm * 4;
    const int nbB = wn * 4;

    for (int i = 0; i < 32; i++) {
        CP_WAIT2();
        __syncthreads();

        if (i + 3 < 32) {
            uint32_t sb = sbase + ((i + 3) & 3) * STAGE_BYTES;
#pragma unroll
            for (int j = 0; j < 8; j++)
                CP_ASYNC16(sb + soff[j], gptr[j] + (size_t)(i + 3) * 64);
        }
        CP_COMMIT();

        const uint32_t st = sbase + (i & 3) * STAGE_BYTES;
#pragma unroll
        for (int kb = 0; kb < 2; kb++) {
            uint4 ah[4], bh[4];
#pragma unroll
            for (int mt = 0; mt < 4; mt++)
                LDS128(ah[mt], st + (uint32_t)((kb * 8 + mbB + mt) * 512) + lane * 16);
#pragma unroll
            for (int q = 0; q < 4; q++)
                LDS128(bh[q], st + (uint32_t)(8192 + (kb * 8 + nbB + q) * 512) + lane * 16);
#pragma unroll
            for (int mt = 0; mt < 4; mt++) {
#pragma unroll
                for (int nt = 0; nt < 8; nt++) {
                    const uint4& B = bh[nt >> 1];
                    uint32_t b0 = (nt & 1) ? B.z : B.x;
                    uint32_t b1 = (nt & 1) ? B.w : B.y;
                    mma16816_f16(acc[mt][nt], ah[mt], b0, b1);
                }
            }
        }
    }

    // ---- tail: drain pipeline, then reuse smem for staging ----
    CP_WAIT0();
    __syncthreads();

    const uint32_t tauT = sbase;                  // [128][68] float
    const uint32_t fT   = sbase + 128 * TPAD * 4; // [128][68] float
    const int g  = lane >> 2;
    const int tg = lane & 3;

    // Phase 1: scatter raw pre-activations to smem
    // acc[mt][nt][0..1] = (tau_pre, f_pre) at (row wm*64+mt*16+g, j = wn*32+nt*4+tg)
    // acc[mt][nt][2..3] same at row+8.
#pragma unroll
    for (int mt = 0; mt < 4; mt++) {
        int r0 = wm * 64 + mt * 16 + g;
        int r1 = r0 + 8;
#pragma unroll
        for (int nt = 0; nt < 8; nt++) {
            int jj = wn * 32 + nt * 4 + tg;
            asm volatile("st.shared.f32 [%0], %1;" :: "r"(tauT + (uint32_t)(r0 * TPAD + jj) * 4), "f"(acc[mt][nt][0]) : "memory");
            asm volatile("st.shared.f32 [%0], %1;" :: "r"(fT   + (uint32_t)(r0 * TPAD + jj) * 4), "f"(acc[mt][nt][1]) : "memory");
            asm volatile("st.shared.f32 [%0], %1;" :: "r"(tauT + (uint32_t)(r1 * TPAD + jj) * 4), "f"(acc[mt][nt][2]) : "memory");
            asm volatile("st.shared.f32 [%0], %1;" :: "r"(fT   + (uint32_t)(r1 * TPAD + jj) * 4), "f"(acc[mt][nt][3]) : "memory");
        }
    }
    __syncthreads();

    // Phase 2: coalesced writeout, 128 threads: half-warp owns a row, 16 iters.
    const int jj4 = tid & 15;
    const int rgrp = tid >> 4;                    // 0..7
    const int jbase = bn * 64;
    const float4 bt4 = ((const float4*)b_tau)[jbase / 4 + jj4];
    const float4 bi4 = ((const float4*)b_in)[jbase / 4 + jj4];

#pragma unroll
    for (int quarter = 0; quarter < 4; quarter++) {
        float4 h4s[4];
#pragma unroll
        for (int u = 0; u < 4; u++) {
            int r = rgrp + (quarter * 4 + u) * 8;
            size_t row = (size_t)bm * 128 + r;
            h4s[u] = *((const float4*)(hin + row * H_DIM + jbase) + jj4);
        }
#pragma unroll
        for (int u = 0; u < 4; u++) {
            int r = rgrp + (quarter * 4 + u) * 8;
            size_t row = (size_t)bm * 128 + r;

            float4 tp, fp;
            LDS128(*(uint4*)&tp, tauT + (uint32_t)(r * TPAD + jj4 * 4) * 4);
            LDS128(*(uint4*)&fp, fT   + (uint32_t)(r * TPAD + jj4 * 4) * 4);
            float4 h4 = h4s[u];

            float4 tv, yv;
            float s = 0.f, q = 0.f;
            {
                const float* ptp = &tp.x; const float* pfp = &fp.x;
                const float* ph = &h4.x; const float* pbt = &bt4.x; const float* pbi = &bi4.x;
                float* ptv = &tv.x; float* pyv = &yv.x;
#pragma unroll
                for (int c = 0; c < 4; c++) {
                    float tau = 0.5f + 4.5f / (1.0f + __expf(-(ptp[c] + pbt[c])));
                    float f   = tanhf(pfp[c] + pbi[c]);
                    float yy  = ph[c] + 0.1f * (f - ph[c]) / tau;
                    ptv[c] = tau; pyv[c] = yy;
                    s += yy; q += yy * yy;
                }
            }
            *((float4*)(out_tau + row * H_DIM + jbase) + jj4) = tv;
            *((float4*)(g_Y + row * H_DIM + jbase) + jj4) = yv;

            s += __shfl_xor_sync(0xffffffffu, s, 1);
            q += __shfl_xor_sync(0xffffffffu, q, 1);
            s += __shfl_xor_sync(0xffffffffu, s, 2);
            q += __shfl_xor_sync(0xffffffffu, q, 2);
            s += __shfl_xor_sync(0xffffffffu, s, 4);
            q += __shfl_xor_sync(0xffffffffu, q, 4);
            s += __shfl_xor_sync(0xffffffffu, s, 8);
            q += __shfl_xor_sync(0xffffffffu, q, 8);
            if (jj4 == 0)
                g_Spart[row * 8 + bn] = make_float2(s, q);
        }
    }
}

// ---------------------------------------------------------------------------
// Finalize (verbatim): 4 rows/block, 2 float4/thread, y-loads early.
// ---------------------------------------------------------------------------
__global__ __launch_bounds__(256)
void finalize_kernel(const float* __restrict__ gamma, const float* __restrict__ beta,
                     float* __restrict__ out_h) {
    const int tid = threadIdx.x;
    const size_t row0 = (size_t)blockIdx.x * 4;
    const int r = tid >> 6;
    const int t = tid & 63;
    const size_t row = row0 + r;

    float4 ya = *((const float4*)(g_Y + row * H_DIM) + t);
    float4 yb = *((const float4*)(g_Y + row * H_DIM) + t + 64);

    __shared__ float2 mv[4];
    if (tid < 32) {
        int rr = tid >> 3, part = tid & 7;
        float2 p = g_Spart[(row0 + rr) * 8 + part];
        float s = p.x, q = p.y;
        s += __shfl_xor_sync(0xffffffffu, s, 1);
        q += __shfl_xor_sync(0xffffffffu, q, 1);
        s += __shfl_xor_sync(0xffffffffu, s, 2);
        q += __shfl_xor_sync(0xffffffffu, q, 2);
        s += __shfl_xor_sync(0xffffffffu, s, 4);
        q += __shfl_xor_sync(0xffffffffu, q, 4);
        if (part == 0) {
            float mu  = s * (1.0f / H_DIM);
            float var = q * (1.0f / H_DIM) - mu * mu;
            mv[rr] = make_float2(mu, rsqrtf(var + 1e-5f));
        }
    }
    __syncthreads();

    float mu  = mv[r].x;
    float inv = mv[r].y;

    float4 ga = ((const float4*)gamma)[t];
    float4 gb = ((const float4*)gamma)[t + 64];
    float4 ba = ((const float4*)beta)[t];
    float4 bb = ((const float4*)beta)[t + 64];

    float4 oa, ob;
    oa.x = (ya.x - mu) * inv * ga.x + ba.x;
    oa.y = (ya.y - mu) * inv * ga.y + ba.y;
    oa.z = (ya.z - mu) * inv * ga.z + ba.z;
    oa.w = (ya.w - mu) * inv * ga.w + ba.w;
    ob.x = (yb.x - mu) * inv * gb.x + bb.x;
    ob.y = (yb.y - mu) * inv * gb.y + bb.y;
    ob.z = (yb.z - mu) * inv * gb.z + bb.z;
    ob.w = (yb.w - mu) * inv * gb.w + bb.w;

    *((float4*)(out_h + row * H_DIM) + t) = oa;
    *((float4*)(out_h + row * H_DIM) + t + 64) = ob;
}

// ---------------------------------------------------------------------------
extern "C" void kernel_launch(void* const* d_in, const int* in_sizes, int n_in,
                              void* d_out, int out_size) {
    const float* x     = (const float*)d_in[0];
    const float* h     = (const float*)d_in[1];
    const float* W_in  = (const float*)d_in[2];
    const float* b_in  = (const float*)d_in[3];
    const float* W_rec = (const float*)d_in[4];
    const float* W_tau = (const float*)d_in[5];
    const float* b_tau = (const float*)d_in[6];
    const float* gamma = (const float*)d_in[7];
    const float* beta  = (const float*)d_in[8];

    const int B = in_sizes[0] / I_DIM;    // 65536

    float* out = (float*)d_out;
    float* out_h   = out;
    float* out_tau = out + (size_t)B * H_DIM;

    prep_kernel<<<B / 16 + 512, 256>>>(x, h, W_in, W_rec, W_tau);

    cudaFuncSetAttribute(gemm_mma_kernel,
                         cudaFuncAttributeMaxDynamicSharedMemorySize, SMEM_REQ);
    dim3 ggrid(NTOT / 128, B / 128);      // (8, 512)
    gemm_mma_kernel<<<ggrid, 128, SMEM_REQ>>>(h, b_in, b_tau, out_tau);

    finalize_kernel<<<B / 4, 256>>>(gamma, beta, out_h);
}